// round 4
// baseline (speedup 1.0000x reference)
#include <cuda_runtime.h>

#define G   16
#define Bsz 2
#define C   256
#define Cg  16
#define H   24
#define Wd  24
#define HW  576
#define AC  6400
#define ACg 400
#define EPSV 1e-5f

// -------- device scratch (no allocations allowed) --------
__device__ float g_h1[G * Bsz * C * HW];   // 18.9 MB
__device__ float g_pooled[G * Bsz * AC];
__device__ float g_aff[G * Bsz * G];

// ---------- packed f32x2 helpers ----------
__device__ __forceinline__ unsigned long long pack2(float x, float y) {
    unsigned long long r;
    asm("mov.b64 %0, {%1,%2};" : "=l"(r) : "f"(x), "f"(y));
    return r;
}
__device__ __forceinline__ float2 unpack2(unsigned long long v) {
    float2 f;
    asm("mov.b64 {%0,%1}, %2;" : "=f"(f.x), "=f"(f.y) : "l"(v));
    return f;
}
__device__ __forceinline__ void fma2(unsigned long long& acc,
                                     unsigned long long a, unsigned long long b) {
    asm("fma.rn.f32x2 %0, %1, %2, %0;" : "+l"(acc) : "l"(a), "l"(b));
}
__device__ __forceinline__ unsigned long long fma2o(unsigned long long a,
                                                    unsigned long long b,
                                                    unsigned long long c) {
    unsigned long long d;
    asm("fma.rn.f32x2 %0, %1, %2, %3;" : "=l"(d) : "l"(a), "l"(b), "l"(c));
    return d;
}

// ============================================================
// Kernel 1: grouped 3x3 conv + BN + ReLU -> g_h1 (f32x2 over co-pairs)
// grid (k=16, b=2, g=16), block 192 = 8 co-pairs x 24 rows
// ============================================================
__global__ __launch_bounds__(192) void k1_conv3(
    const float* __restrict__ x,
    const float* __restrict__ W1,
    const float* __restrict__ g1, const float* __restrict__ b1,
    const float* __restrict__ m1, const float* __restrict__ v1)
{
    const int k = blockIdx.x, b = blockIdx.y, g = blockIdx.z;
    __shared__ float tile[8 * 26 * 27];
    __shared__ float wsm[16 * 16 * 9];

    const int tid = threadIdx.x;

    const float* wsrc = W1 + (g * 256 + k * 16) * 144;
    for (int i = tid; i < 2304; i += 192) wsm[i] = wsrc[i];
    for (int i = tid; i < 8 * 26 * 27; i += 192) tile[i] = 0.f;

    const int cop = tid / 24;
    const int row = tid % 24;
    const float* w0row = wsm + (2 * cop) * 144;
    const float* w1row = wsm + (2 * cop + 1) * 144;

    unsigned long long acc[24];
#pragma unroll
    for (int j = 0; j < 24; ++j) acc[j] = 0ull;

    for (int half = 0; half < 2; ++half) {
        __syncthreads();
        for (int i = tid; i < 8 * 576; i += 192) {
            int cil = i / 576, p = i % 576;
            int y = p / 24, xx = p % 24;
            tile[cil * 702 + (y + 1) * 27 + (xx + 1)] =
                x[(b * 256 + k * 16 + half * 8 + cil) * 576 + p];
        }
        __syncthreads();

        for (int cil = 0; cil < 8; ++cil) {
            const int ci = half * 8 + cil;
            unsigned long long wp[9];
#pragma unroll
            for (int t = 0; t < 9; ++t)
                wp[t] = pack2(w0row[ci * 9 + t], w1row[ci * 9 + t]);

#pragma unroll
            for (int ky = 0; ky < 3; ++ky) {
                const float* rp = tile + cil * 702 + (row + ky) * 27;
                unsigned long long s0 = pack2(rp[0], rp[0]);
                unsigned long long s1 = pack2(rp[1], rp[1]);
#pragma unroll
                for (int j = 0; j < 24; ++j) {
                    float cc = rp[j + 2];
                    unsigned long long s2 = pack2(cc, cc);
                    fma2(acc[j], wp[ky * 3 + 0], s0);
                    fma2(acc[j], wp[ky * 3 + 1], s1);
                    fma2(acc[j], wp[ky * 3 + 2], s2);
                    s0 = s1; s1 = s2;
                }
            }
        }
    }

    const int co0 = 2 * cop;
    const int ch0 = g * 256 + k * 16 + co0;
    const float sc0 = g1[ch0] * rsqrtf(v1[ch0] + EPSV);
    const float bi0 = b1[ch0] - m1[ch0] * sc0;
    const float sc1 = g1[ch0 + 1] * rsqrtf(v1[ch0 + 1] + EPSV);
    const float bi1 = b1[ch0 + 1] - m1[ch0 + 1] * sc1;

    float* op0 = g_h1 + (((g * 2 + b) * 256 + k * 16 + co0) * 576) + row * 24;
    float* op1 = op0 + 576;
#pragma unroll
    for (int j = 0; j < 24; ++j) {
        float2 f = unpack2(acc[j]);
        op0[j] = fmaxf(fmaf(f.x, sc0, bi0), 0.f);
        op1[j] = fmaxf(fmaf(f.y, sc1, bi1), 0.f);
    }
}

// ============================================================
// Kernel 2: grouped 1x1 conv + BN + ReLU + avg-pool.
// grid (k=16, b=2, g=16), 256 threads; threads 0..199 each own TWO acs
// (t and t+200) so every LDS.128 of h feeds 8 FFMA2.
// ============================================================
__global__ __launch_bounds__(256) void k2_pool(
    const float* __restrict__ W2,
    const float* __restrict__ g2, const float* __restrict__ b2,
    const float* __restrict__ m2, const float* __restrict__ v2)
{
    const int k = blockIdx.x, b = blockIdx.y, g = blockIdx.z;
    __shared__ ulonglong2 hsm[16 * 144];   // 16 ci x 576 pos = 36 KB

    const int tid = threadIdx.x;
    {
        const float4* src4 = reinterpret_cast<const float4*>(
            g_h1 + ((g * 2 + b) * 256 + k * 16) * 576);
        float4* dst4 = reinterpret_cast<float4*>(hsm);
        for (int i = tid; i < 2304; i += 256) dst4[i] = src4[i];
    }
    __syncthreads();

    if (tid < 200) {
        const int ac0 = k * 400 + tid;
        const int ac1 = ac0 + 200;
        const int pi0 = g * 6400 + ac0;
        const int pi1 = pi0 + 200;

        unsigned long long w0[16], w1[16];
        {
            const float4* wa = reinterpret_cast<const float4*>(W2 + (size_t)pi0 * 16);
            const float4* wb = reinterpret_cast<const float4*>(W2 + (size_t)pi1 * 16);
#pragma unroll
            for (int i = 0; i < 4; ++i) {
                float4 ta = wa[i];
                w0[4 * i + 0] = pack2(ta.x, ta.x);
                w0[4 * i + 1] = pack2(ta.y, ta.y);
                w0[4 * i + 2] = pack2(ta.z, ta.z);
                w0[4 * i + 3] = pack2(ta.w, ta.w);
            }
#pragma unroll
            for (int i = 0; i < 4; ++i) {
                float4 tb = wb[i];
                w1[4 * i + 0] = pack2(tb.x, tb.x);
                w1[4 * i + 1] = pack2(tb.y, tb.y);
                w1[4 * i + 2] = pack2(tb.z, tb.z);
                w1[4 * i + 3] = pack2(tb.w, tb.w);
            }
        }

        const float sc0 = g2[pi0] * rsqrtf(v2[pi0] + EPSV);
        const float bi0 = b2[pi0] - m2[pi0] * sc0;
        const float sc1 = g2[pi1] * rsqrtf(v2[pi1] + EPSV);
        const float bi1 = b2[pi1] - m2[pi1] * sc1;
        const unsigned long long sc0p = pack2(sc0, sc0), bi0p = pack2(bi0, bi0);
        const unsigned long long sc1p = pack2(sc1, sc1), bi1p = pack2(bi1, bi1);
        const float border0 = fmaxf(bi0, 0.f);
        const float border1 = fmaxf(bi1, 0.f);

        float sum0 = 0.f, sum1 = 0.f;
        for (int p4 = 0; p4 < 144; ++p4) {
            unsigned long long a01 = 0ull, a23 = 0ull;
            unsigned long long c01 = 0ull, c23 = 0ull;
#pragma unroll
            for (int ci = 0; ci < 16; ++ci) {
                ulonglong2 h = hsm[ci * 144 + p4];   // LDS.128 broadcast
                fma2(a01, w0[ci], h.x);
                fma2(a23, w0[ci], h.y);
                fma2(c01, w1[ci], h.x);
                fma2(c23, w1[ci], h.y);
            }
            float2 t01 = unpack2(fma2o(a01, sc0p, bi0p));
            float2 t23 = unpack2(fma2o(a23, sc0p, bi0p));
            sum0 += (fmaxf(t01.x, 0.f) + fmaxf(t01.y, 0.f))
                  + (fmaxf(t23.x, 0.f) + fmaxf(t23.y, 0.f));
            float2 u01 = unpack2(fma2o(c01, sc1p, bi1p));
            float2 u23 = unpack2(fma2o(c23, sc1p, bi1p));
            sum1 += (fmaxf(u01.x, 0.f) + fmaxf(u01.y, 0.f))
                  + (fmaxf(u23.x, 0.f) + fmaxf(u23.y, 0.f));
        }
        float* dst = g_pooled + (g * 2 + b) * 6400;
        dst[ac0] = (sum0 + 100.f * border0) * (1.f / 676.f);
        dst[ac1] = (sum1 + 100.f * border1) * (1.f / 676.f);
    }
}

// ============================================================
// Kernel 3: affinity rows. grid 32 = (i*2+b), 512 thr = 16 warps
// ============================================================
__global__ __launch_bounds__(512) void k3_aff()
{
    const int ib = blockIdx.x;
    const int i = ib >> 1;
    const int wrp = threadIdx.x >> 5, lane = threadIdx.x & 31;
    const float* base = g_pooled + ib * 6400;
    const float* pa = base + i * 400;
    const float* pb = base + wrp * 400;
    float s = 0.f;
    for (int m = lane; m < 400; m += 32) s += pa[m] * pb[m];
#pragma unroll
    for (int o = 16; o; o >>= 1) s += __shfl_xor_sync(0xffffffffu, s, o);
    if (lane == 0) g_aff[ib * 16 + wrp] = s * (1.f / 16.f);
}

// ============================================================
// Kernel 4: z = aff . h1 -> out, float4 vectorized
// grid (cg=16, q=2, i=16), 144 threads, each owns 4 positions
// ============================================================
__global__ __launch_bounds__(144) void k4_out(float* __restrict__ out)
{
    const int cg = blockIdx.x, q = blockIdx.y, i = blockIdx.z;
    __shared__ float a0[16], a1[16];
    const int tid = threadIdx.x;
    if (tid < 16)      a0[tid]      = g_aff[(i * 2 + 0) * 16 + tid];
    else if (tid < 32) a1[tid - 16] = g_aff[(i * 2 + 1) * 16 + (tid - 16)];
    __syncthreads();

    const float4* hb = reinterpret_cast<const float4*>(
        g_h1 + ((i * 2 + q) * 256 + cg) * 576) + tid;
    float4 acc0 = {0.f, 0.f, 0.f, 0.f};
    float4 acc1 = {0.f, 0.f, 0.f, 0.f};
#pragma unroll
    for (int kk = 0; kk < 16; ++kk) {
        float4 hv = hb[kk * 16 * 144];
        float w0 = a0[kk], w1 = a1[kk];
        acc0.x = fmaf(w0, hv.x, acc0.x); acc0.y = fmaf(w0, hv.y, acc0.y);
        acc0.z = fmaf(w0, hv.z, acc0.z); acc0.w = fmaf(w0, hv.w, acc0.w);
        acc1.x = fmaf(w1, hv.x, acc1.x); acc1.y = fmaf(w1, hv.y, acc1.y);
        acc1.z = fmaf(w1, hv.z, acc1.z); acc1.w = fmaf(w1, hv.w, acc1.w);
    }
    const int ch = (i * 2 + q) * 16 + cg;
    float4* o0 = reinterpret_cast<float4*>(out + (0 * 512 + ch) * 576) + tid;
    float4* o1 = reinterpret_cast<float4*>(out + (1 * 512 + ch) * 576) + tid;
    *o0 = acc0;
    *o1 = acc1;
}

// ============================================================
extern "C" void kernel_launch(void* const* d_in, const int* in_sizes, int n_in,
                              void* d_out, int out_size)
{
    const float* x  = (const float*)d_in[0];
    const float* W1 = (const float*)d_in[1];
    const float* g1 = (const float*)d_in[2];
    const float* b1 = (const float*)d_in[3];
    const float* m1 = (const float*)d_in[4];
    const float* v1 = (const float*)d_in[5];
    const float* W2 = (const float*)d_in[6];
    const float* g2 = (const float*)d_in[7];
    const float* b2 = (const float*)d_in[8];
    const float* m2 = (const float*)d_in[9];
    const float* v2 = (const float*)d_in[10];
    float* out = (float*)d_out;

    dim3 grid(16, 2, 16);
    k1_conv3<<<grid, 192>>>(x, W1, g1, b1, m1, v1);
    k2_pool <<<grid, 256>>>(W2, g2, b2, m2, v2);
    k3_aff  <<<32, 512>>>();
    k4_out  <<<grid, 144>>>(out);
}